// round 8
// baseline (speedup 1.0000x reference)
#include <cuda_runtime.h>
#include <cstdint>

typedef unsigned long long ull;

#define NMAX   100000
#define EMAX   2000000
#define F_IN   500
#define H1     64
#define C_OUT  40
#define KC     100        // k-chunk for GEMM1 (double-buffered)
#define KP4    (KC / 4)   // double-k-pair steps per chunk = 25
#define KXP    104        // padded x-row stride in smem (floats), 16B-divisible
#define BM     64         // rows per block in GEMM1
#define NCHUNK (F_IN / KC)
#define GT     256        // GEMM1 threads (8 warps x 8 rows)
#define WSZ    (KP4 * H1 * 2)   // packed-W ull elems per chunk buffer = 3200
#define NBMAX  128

// Scratch (allocation-free rule: __device__ globals)
__device__ int   g_degi[NMAX];
__device__ float g_dinv[NMAX];
__device__ float g_h1  [(size_t)NMAX * H1];
__device__ float g_t2  [(size_t)NMAX * C_OUT];
__device__ int   g_src [EMAX];
__device__ int   g_dst [EMAX];
__device__ int   g_adj [EMAX];
__device__ int   g_row [NMAX + 1];
__device__ int   g_cur [NMAX];
__device__ int   g_bsum[NBMAX];
__device__ int   g_boff[NBMAX];
__device__ int   g_is64;

// ---------- packed-f32 helpers ----------
__device__ __forceinline__ ull pack2(float lo, float hi) {
    ull r;
    asm("mov.b64 %0, {%1, %2};" : "=l"(r) : "f"(lo), "f"(hi));
    return r;
}
__device__ __forceinline__ void ffma2(ull& d, ull a, ull b) {
    asm("fma.rn.f32x2 %0, %1, %2, %0;" : "+l"(d) : "l"(a), "l"(b));
}

// ---------- edge dtype detection ----------
__global__ void k_detect(const void* __restrict__ ei, int E, int n) {
    const long long* p = (const long long*)ei;
    int m = min(4096, E);
    int bad = 0;
    for (int i = threadIdx.x; i < m; i += blockDim.x) {
        long long v = p[i];
        if (v < 0 || v >= (long long)n) bad = 1;
    }
    bad = __syncthreads_or(bad);
    if (threadIdx.x == 0) g_is64 = bad ? 0 : 1;
}

__global__ void k_zero(int n) {
    int i = blockIdx.x * blockDim.x + threadIdx.x;
    if (i < n) g_degi[i] = 0;
}

// ---------- fused: edge int32 conversion + degree histogram ----------
__global__ void k_convert_hist(const void* __restrict__ ei, int E) {
    int i = blockIdx.x * blockDim.x + threadIdx.x;
    if (i >= E) return;
    int s, d;
    if (g_is64) {
        const long long* p = (const long long*)ei;
        s = (int)p[i];
        d = (int)p[E + i];
    } else {
        const int* p = (const int*)ei;
        s = p[i];
        d = p[E + i];
    }
    g_src[i] = s;
    g_dst[i] = d;
    atomicAdd(&g_degi[d], 1);
}

// ---------- GEMM1 (launch #4 -> profiled): h1 = dinv * (x @ W1) ----------
// warp = 8 rows x 64 cols; 2 k-pairs per step; W pre-packed + interleaved
// so all inner-loop LDS are 16B with immediate offsets. Double-buffered.
__global__ void __launch_bounds__(GT)
k_gemm1(const float* __restrict__ x, const float* __restrict__ W, int n) {
    extern __shared__ float sm[];
    float* xs0 = sm;                               // [BM][KXP]
    float* xs1 = xs0 + BM * KXP;                   // [BM][KXP]
    ull*   ws0 = (ull*)(xs1 + BM * KXP);           // [KP4][H1][2]
    ull*   ws1 = ws0 + WSZ;

    const int tid  = threadIdx.x;
    const int lane = tid & 31;
    const int wrow = (tid >> 5) << 3;              // warp's first local row
    const int row0 = blockIdx.x * BM;

    ull acc[8][2];
    #pragma unroll
    for (int r = 0; r < 8; r++) { acc[r][0] = 0ull; acc[r][1] = 0ull; }

    const float4* __restrict__ x4 = (const float4*)x;   // F_IN/4 = 125 per row

    // ---- stage chunk 0 ----
    #pragma unroll 1
    for (int i = tid; i < BM * (KC / 4); i += GT) {      // x as float4
        int r = i / (KC / 4);
        int j = i - r * (KC / 4);
        int row = row0 + r;
        ((float4*)xs0)[r * (KXP / 4) + j] =
            (row < n) ? x4[(size_t)row * (F_IN / 4) + j]
                      : make_float4(0.f, 0.f, 0.f, 0.f);
    }
    #pragma unroll 1
    for (int i = tid; i < KP4 * H1; i += GT) {           // packed W (interleaved)
        int kp2 = i >> 6;
        int c   = i & 63;
        int kb  = 4 * kp2;
        ull w0 = pack2(W[(kb)     * H1 + c], W[(kb + 1) * H1 + c]);
        ull w1 = pack2(W[(kb + 2) * H1 + c], W[(kb + 3) * H1 + c]);
        ((ulonglong2*)ws0)[kp2 * H1 + c] = make_ulonglong2(w0, w1);
    }
    __syncthreads();

    for (int c = 0; c < NCHUNK; c++) {
        const float* xcur = (c & 1) ? xs1 : xs0;
        float*       xnxt = (c & 1) ? xs0 : xs1;
        const ull*   wcur = (c & 1) ? ws1 : ws0;
        ull*         wnxt = (c & 1) ? ws0 : ws1;

        if (c + 1 < NCHUNK) {
            const int kc1 = (c + 1) * KC;
            #pragma unroll 1
            for (int i = tid; i < BM * (KC / 4); i += GT) {
                int r = i / (KC / 4);
                int j = i - r * (KC / 4);
                int row = row0 + r;
                ((float4*)xnxt)[r * (KXP / 4) + j] =
                    (row < n) ? x4[(size_t)row * (F_IN / 4) + kc1 / 4 + j]
                              : make_float4(0.f, 0.f, 0.f, 0.f);
            }
            #pragma unroll 1
            for (int i = tid; i < KP4 * H1; i += GT) {
                int kp2 = i >> 6;
                int cc  = i & 63;
                int kb  = kc1 + 4 * kp2;
                ull w0 = pack2(W[(kb)     * H1 + cc], W[(kb + 1) * H1 + cc]);
                ull w1 = pack2(W[(kb + 2) * H1 + cc], W[(kb + 3) * H1 + cc]);
                ((ulonglong2*)wnxt)[kp2 * H1 + cc] = make_ulonglong2(w0, w1);
            }
        }

        // hoisted base pointers -> inner LDS all use immediate offsets
        const ulonglong2* wA = (const ulonglong2*)wcur + lane;        // col lane
        const ulonglong2* wB = (const ulonglong2*)wcur + 32 + lane;   // col lane+32
        const ulonglong2* xr[8];
        #pragma unroll
        for (int r = 0; r < 8; r++)
            xr[r] = (const ulonglong2*)(xcur + (wrow + r) * KXP);

        #pragma unroll
        for (int kp2 = 0; kp2 < KP4; kp2++) {
            const ulonglong2 wa = wA[kp2 * H1];
            const ulonglong2 wb = wB[kp2 * H1];
            ulonglong2 xv[8];
            #pragma unroll
            for (int r = 0; r < 8; r++) xv[r] = xr[r][kp2];   // 16B broadcast
            #pragma unroll
            for (int r = 0; r < 8; r++) {
                ffma2(acc[r][0], xv[r].x, wa.x);
                ffma2(acc[r][1], xv[r].x, wb.x);
            }
            #pragma unroll
            for (int r = 0; r < 8; r++) {
                ffma2(acc[r][0], xv[r].y, wa.y);
                ffma2(acc[r][1], xv[r].y, wb.y);
            }
        }
        __syncthreads();
    }

    #pragma unroll
    for (int r = 0; r < 8; r++) {
        const int row = row0 + wrow + r;
        if (row < n) {
            const float dd = rsqrtf((float)g_degi[row] + 1.0f);  // +1 self-loop
            if (lane == 0) g_dinv[row] = dd;
            float2 v0 = *(float2*)&acc[r][0];
            float2 v1 = *(float2*)&acc[r][1];
            g_h1[(size_t)row * H1 + lane]      = dd * (v0.x + v0.y);
            g_h1[(size_t)row * H1 + 32 + lane] = dd * (v1.x + v1.y);
        }
    }
}

// ---------- CSR build: block scan over degrees ----------
__global__ void __launch_bounds__(1024)
k_scanA(int n) {
    __shared__ int s0[1024], s1[1024];
    const int tid = threadIdx.x;
    const int i = blockIdx.x * 1024 + tid;
    int v = (i < n) ? g_degi[i] : 0;
    s0[tid] = v;
    __syncthreads();
    int* a = s0; int* b = s1;
    #pragma unroll
    for (int off = 1; off < 1024; off <<= 1) {
        b[tid] = a[tid] + ((tid >= off) ? a[tid - off] : 0);
        __syncthreads();
        int* t = a; a = b; b = t;
    }
    if (i < n) g_row[i] = a[tid] - v;
    if (tid == 1023) g_bsum[blockIdx.x] = a[1023];
}
__global__ void __launch_bounds__(NBMAX)
k_scanB(int nb) {
    __shared__ int s0[NBMAX], s1[NBMAX];
    const int tid = threadIdx.x;
    int v = (tid < nb) ? g_bsum[tid] : 0;
    s0[tid] = v;
    __syncthreads();
    int* a = s0; int* b = s1;
    #pragma unroll
    for (int off = 1; off < NBMAX; off <<= 1) {
        b[tid] = a[tid] + ((tid >= off) ? a[tid - off] : 0);
        __syncthreads();
        int* t = a; a = b; b = t;
    }
    if (tid < nb) g_boff[tid] = a[tid] - v;
}
__global__ void k_scanC(int n, int E) {
    int i = blockIdx.x * blockDim.x + threadIdx.x;
    if (i < n) {
        int r = g_row[i] + g_boff[i >> 10];
        g_row[i] = r;
        g_cur[i] = r;
    }
    if (i == 0) g_row[n] = E;
}
__global__ void k_fill(int E) {
    int e = blockIdx.x * blockDim.x + threadIdx.x;
    if (e >= E) return;
    int pos = atomicAdd(&g_cur[g_dst[e]], 1);
    g_adj[pos] = g_src[e];
}

// ---------- fused layer-1 aggregate + bias + relu + GEMM2: warp per node ----------
__global__ void __launch_bounds__(256)
k_l1(const float* __restrict__ b1, const float* __restrict__ W2, int n) {
    __shared__ float W2s[H1 * C_OUT];
    __shared__ float b1s[H1];
    const int tid = threadIdx.x;
    for (int i = tid; i < H1 * C_OUT; i += 256) W2s[i] = W2[i];
    if (tid < H1) b1s[tid] = b1[tid];
    __syncthreads();

    const int lane = tid & 31;
    const int d = blockIdx.x * 8 + (tid >> 5);
    if (d >= n) return;

    const int beg = g_row[d];
    const int end = g_row[d + 1];
    const float2* __restrict__ h2 = (const float2*)g_h1;

    float2 a0 = h2[(size_t)d * 32 + lane];   // self-loop
    float2 a1 = make_float2(0.f, 0.f);
    float2 a2 = make_float2(0.f, 0.f);
    float2 a3 = make_float2(0.f, 0.f);

    int i = beg;
    for (; i + 8 <= end; i += 8) {
        int s[8];
        #pragma unroll
        for (int j = 0; j < 8; j++) s[j] = g_adj[i + j];
        float2 v[8];
        #pragma unroll
        for (int j = 0; j < 8; j++) v[j] = h2[(size_t)s[j] * 32 + lane];
        a0.x += v[0].x; a0.y += v[0].y;  a1.x += v[1].x; a1.y += v[1].y;
        a2.x += v[2].x; a2.y += v[2].y;  a3.x += v[3].x; a3.y += v[3].y;
        a0.x += v[4].x; a0.y += v[4].y;  a1.x += v[5].x; a1.y += v[5].y;
        a2.x += v[6].x; a2.y += v[6].y;  a3.x += v[7].x; a3.y += v[7].y;
    }
    for (; i < end; i++) {
        float2 v = h2[(size_t)g_adj[i] * 32 + lane];
        a0.x += v.x; a0.y += v.y;
    }
    a0.x += a1.x + a2.x + a3.x;
    a0.y += a1.y + a2.y + a3.y;

    const float dd = g_dinv[d];
    const float hx = fmaxf(a0.x * dd + b1s[2 * lane],     0.0f);
    const float hy = fmaxf(a0.y * dd + b1s[2 * lane + 1], 0.0f);

    float c0 = 0.0f, c1 = 0.0f;
    #pragma unroll
    for (int k2 = 0; k2 < 32; k2++) {
        const float ha = __shfl_sync(0xffffffffu, hx, k2);
        const float hb = __shfl_sync(0xffffffffu, hy, k2);
        c0 += ha * W2s[(2 * k2)     * C_OUT + lane];
        c0 += hb * W2s[(2 * k2 + 1) * C_OUT + lane];
        if (lane < 8) {
            c1 += ha * W2s[(2 * k2)     * C_OUT + 32 + lane];
            c1 += hb * W2s[(2 * k2 + 1) * C_OUT + 32 + lane];
        }
    }
    g_t2[(size_t)d * C_OUT + lane] = c0 * dd;
    if (lane < 8) g_t2[(size_t)d * C_OUT + 32 + lane] = c1 * dd;
}

// ---------- fused layer-2 aggregate + bias + relu + log_softmax: warp per node ----------
__global__ void __launch_bounds__(256)
k_l2(float* __restrict__ out, const float* __restrict__ b2, int n) {
    __shared__ float b2s[C_OUT];
    const int tid = threadIdx.x;
    if (tid < C_OUT) b2s[tid] = b2[tid];
    __syncthreads();

    const int lane = tid & 31;
    const int d = blockIdx.x * 8 + (tid >> 5);
    if (d >= n) return;

    const int beg = g_row[d];
    const int end = g_row[d + 1];
    const bool lo8 = (lane < 8);

    float aa0 = g_t2[(size_t)d * C_OUT + lane];
    float ab0 = lo8 ? g_t2[(size_t)d * C_OUT + 32 + lane] : 0.0f;
    float aa1 = 0.f, ab1 = 0.f, aa2 = 0.f, ab2 = 0.f, aa3 = 0.f, ab3 = 0.f;

    int i = beg;
    for (; i + 8 <= end; i += 8) {
        int s[8];
        #pragma unroll
        for (int j = 0; j < 8; j++) s[j] = g_adj[i + j];
        float va[8];
        #pragma unroll
        for (int j = 0; j < 8; j++) va[j] = g_t2[(size_t)s[j] * C_OUT + lane];
        aa0 += va[0]; aa1 += va[1]; aa2 += va[2]; aa3 += va[3];
        aa0 += va[4]; aa1 += va[5]; aa2 += va[6]; aa3 += va[7];
        if (lo8) {
            float vb[8];
            #pragma unroll
            for (int j = 0; j < 8; j++) vb[j] = g_t2[(size_t)s[j] * C_OUT + 32 + lane];
            ab0 += vb[0]; ab1 += vb[1]; ab2 += vb[2]; ab3 += vb[3];
            ab0 += vb[4]; ab1 += vb[5]; ab2 += vb[6]; ab3 += vb[7];
        }
    }
    for (; i < end; i++) {
        int s = g_adj[i];
        aa0 += g_t2[(size_t)s * C_OUT + lane];
        if (lo8) ab0 += g_t2[(size_t)s * C_OUT + 32 + lane];
    }
    aa0 += aa1 + aa2 + aa3;
    ab0 += ab1 + ab2 + ab3;

    const float dd = g_dinv[d];
    const float v0 = fmaxf(aa0 * dd + b2s[lane], 0.0f);
    const float v1 = lo8 ? fmaxf(ab0 * dd + b2s[32 + lane], 0.0f) : -1e30f;

    float m = fmaxf(v0, v1);
    #pragma unroll
    for (int o = 16; o; o >>= 1) m = fmaxf(m, __shfl_xor_sync(0xffffffffu, m, o));
    float s = expf(v0 - m) + (lo8 ? expf(v1 - m) : 0.0f);
    #pragma unroll
    for (int o = 16; o; o >>= 1) s += __shfl_xor_sync(0xffffffffu, s, o);
    const float lse = m + logf(s);

    out[(size_t)d * C_OUT + lane] = v0 - lse;
    if (lo8) out[(size_t)d * C_OUT + 32 + lane] = v1 - lse;
}

extern "C" void kernel_launch(void* const* d_in, const int* in_sizes, int n_in,
                              void* d_out, int out_size) {
    const float* x  = (const float*)d_in[0];
    const void*  ei = d_in[1];
    const float* W1 = (const float*)d_in[2];
    const float* b1 = (const float*)d_in[3];
    const float* W2 = (const float*)d_in[4];
    const float* b2 = (const float*)d_in[5];
    float*       out = (float*)d_out;

    const int n = in_sizes[0] / F_IN;
    const int E = in_sizes[1] / 2;
    const int nb = (n + 1023) / 1024;

    k_detect      <<<1, 256>>>(ei, E, n);                 // launch 1
    k_zero        <<<(n + 255) / 256, 256>>>(n);          // launch 2
    k_convert_hist<<<(E + 255) / 256, 256>>>(ei, E);      // launch 3

    const int smem = (2 * BM * KXP) * (int)sizeof(float)
                   + 2 * WSZ * (int)sizeof(ull);          // ~102KB
    cudaFuncSetAttribute(k_gemm1, cudaFuncAttributeMaxDynamicSharedMemorySize, smem);
    k_gemm1<<<(n + BM - 1) / BM, GT, smem>>>(x, W1, n);   // launch 4 (profiled)

    k_scanA <<<nb, 1024>>>(n);
    k_scanB <<<1, NBMAX>>>(nb);
    k_scanC <<<(n + 255) / 256, 256>>>(n, E);
    k_fill  <<<(E + 255) / 256, 256>>>(E);

    k_l1<<<(n + 7) / 8, 256>>>(b1, W2, n);
    k_l2<<<(n + 7) / 8, 256>>>(out, b2, n);
}